// round 8
// baseline (speedup 1.0000x reference)
#include <cuda_runtime.h>
#include <cuda_fp16.h>

#define NN 20000
#define NE 320000
#define NB 25
#define SEG 800
#define FULLMASK 0xffffffffu
#define CSTF 1e-5f
#define CSRB 148
#define GEMMB 313

#define FMA2(acc, a, b) asm("fma.rn.f32x2 %0, %1, %2, %0;" : "+l"(acc) : "l"(a), "l"(b))
#define PACK2(xx, xv)   asm("mov.b64 %0, {%1, %1};" : "=l"(xx) : "f"(xv))

union U2 { unsigned long long u; float2 f; };

// ---------------- device scratch (static; every call restores zeros) ----------------
__device__ float  g_Q[NN*64];
__device__ __half g_Kh[NN*64];
__device__ __half g_Vh[NN*64];
__device__ float  g_V[NN*64];
__device__ float  g_hidden[NN*64];
__device__ __half g_M1h[(size_t)NN*512];
__device__ __half g_K1h[NN*64];
__device__ float  g_deginv[NN];
__device__ int    g_cnt[NN];               // zeroed inside fused scan phase
__device__ int    g_cur[NN];               // zeroed by k_pass1 tail
__device__ int    g_colptr[NN+1];
__device__ int    g_bsum[NB];
__device__ int    g_boff[NB+1];
__device__ int    g_srow[NE];
__device__ float  g_snorm[NE];
__device__ volatile int g_ph1, g_ph2, g_ph3;   // phase counters (reset in-kernel)

// int64-vs-int32 detect: sample 32 odd words; all zero => int64.
__device__ __forceinline__ void detect64(const int* __restrict__ ei, int tid, int* s64){
  if(tid < 32){
    bool z = (ei[2*(tid*9973)+1] == 0);
    unsigned bal = __ballot_sync(FULLMASK, z);
    if(tid==0) *s64 = (bal == FULLMASK) ? 1 : 0;
  }
}

__device__ __forceinline__ int colp(int i){
  return g_colptr[i] + g_boff[i/SEG];
}

// ============ fused launch: blocks [0,CSRB) build CSR (3 phases, 2 spin barriers),
// ============ blocks [CSRB, CSRB+GEMMB) run the QKV GEMM concurrently.
#define SMEMQKV (16384 + 49152 + 768)
__global__ void __launch_bounds__(256,3) k_fused(const int* __restrict__ ei,
    const float* __restrict__ x,
    const float* __restrict__ Wq, const float* __restrict__ bq,
    const float* __restrict__ Wk, const float* __restrict__ bk,
    const float* __restrict__ Wv, const float* __restrict__ bv){
  extern __shared__ __align__(16) char dsm[];
  int tid = threadIdx.x;
  int bid = blockIdx.x;

  if(bid < CSRB){
    // -------- CSR builder --------
    int* s     = (int*)dsm;                    // SEG
    int* wtot  = (int*)(dsm + SEG*4);          // 8
    int* ps64  = (int*)(dsm + SEG*4 + 32);     // 1
    int* sboff = (int*)(dsm + SEG*4 + 64);     // NB
    detect64(ei, tid, ps64);
    __syncthreads();
    int s64 = *ps64;

    // phase 1: degree histogram
    for(int e = bid*256 + tid; e < NE; e += CSRB*256){
      int c = s64 ? ei[2*(NE+e)] : ei[NE+e];
      atomicAdd(&g_cnt[c], 1);
    }
    __threadfence();
    __syncthreads();
    if(tid == 0){
      atomicAdd((int*)&g_ph1, 1);
      while(g_ph1 < CSRB) {}
    }
    __syncthreads();
    __threadfence();

    // phase 2: per-segment exclusive scan + deginv; zero g_cnt
    if(bid < NB){
      for(int i=tid; i<SEG; i+=256){ s[i] = __ldcg(&g_cnt[bid*SEG+i]); g_cnt[bid*SEG+i] = 0; }
      __syncthreads();
      int c0=0,c1=0,c2=0,c3=0,v=0;
      if(tid < 200){
        c0=s[4*tid]; c1=s[4*tid+1]; c2=s[4*tid+2]; c3=s[4*tid+3];
        v = c0+c1+c2+c3;
      }
      int lane = tid & 31, wid = tid >> 5;
      int xx = v;
      #pragma unroll
      for(int off=1; off<32; off<<=1){ int y=__shfl_up_sync(FULLMASK,xx,off); if(lane>=off) xx+=y; }
      if(lane==31) wtot[wid] = xx;
      __syncthreads();
      if(tid < 32){
        int w = (tid < 7) ? wtot[tid] : 0;
        #pragma unroll
        for(int off=1; off<32; off<<=1){ int y=__shfl_up_sync(FULLMASK,w,off); if(tid>=off) w+=y; }
        if(tid < 7) wtot[tid] = w;
        if(tid == 6) g_bsum[bid] = w;
      }
      __syncthreads();
      if(tid < 200){
        int pre = xx - v + (wid>0 ? wtot[wid-1] : 0);
        int base = bid*SEG + 4*tid;
        g_colptr[base+0] = pre;
        g_colptr[base+1] = pre + c0;
        g_colptr[base+2] = pre + c0 + c1;
        g_colptr[base+3] = pre + c0 + c1 + c2;
        g_deginv[base+0] = c0 ? rsqrtf((float)c0) : 0.f;
        g_deginv[base+1] = c1 ? rsqrtf((float)c1) : 0.f;
        g_deginv[base+2] = c2 ? rsqrtf((float)c2) : 0.f;
        g_deginv[base+3] = c3 ? rsqrtf((float)c3) : 0.f;
      }
    }
    __threadfence();
    __syncthreads();
    if(tid == 0){
      atomicAdd((int*)&g_ph2, 1);
      while(g_ph2 < CSRB) {}
      if(bid == 0) g_ph1 = 0;
    }
    __syncthreads();
    __threadfence();

    // phase 3: block offsets + scatter
    if(tid < 32){
      int v = (tid < NB) ? __ldcg(&g_bsum[tid]) : 0;
      int xx = v;
      #pragma unroll
      for(int off=1; off<32; off<<=1){ int y=__shfl_up_sync(FULLMASK,xx,off); if(tid>=off) xx+=y; }
      if(tid < NB) sboff[tid] = xx - v;
      if(bid == 0){
        if(tid < NB) g_boff[tid] = xx - v;
        if(tid == 31) g_boff[NB] = NE;
      }
    }
    __syncthreads();
    for(int e = bid*256 + tid; e < NE; e += CSRB*256){
      int r = s64 ? ei[2*e]      : ei[e];
      int c = s64 ? ei[2*(NE+e)] : ei[NE+e];
      int pos = __ldcg(&g_colptr[c]) + sboff[c/SEG] + atomicAdd(&g_cur[c], 1);
      g_srow[pos]  = r;
      g_snorm[pos] = __ldcg(&g_deginv[r]) * __ldcg(&g_deginv[c]);
    }
    __threadfence();
    __syncthreads();
    if(tid == 0){
      atomicAdd((int*)&g_ph3, 1);
      if(bid == 0){
        while(g_ph3 < CSRB) {}
        g_ph2 = 0; g_ph3 = 0;
      }
    }
    return;
  }

  // -------- QKV GEMM part --------
  float*  xsf = (float*)dsm;                        // [n*64 + i]
  float2* ws2 = (float2*)(dsm + 16384);             // [m*2048 + i*32 + op]
  float2* bs2 = (float2*)(dsm + 16384 + 49152);     // [m*32 + op]
  int nb = (bid - CSRB)*64;
  for(int idx = tid; idx < 4096; idx += 256){
    int n = idx >> 6, i = idx & 63;
    xsf[idx] = (nb+n < NN) ? x[(nb+n)*64 + i] : 0.f;
    int wi = idx >> 6, wo = idx & 63;
    int wop = wo & 31, hi = wo >> 5;
    ((float*)&ws2[0*2048 + wi*32 + wop])[hi] = Wq[idx];
    ((float*)&ws2[1*2048 + wi*32 + wop])[hi] = Wk[idx];
    ((float*)&ws2[2*2048 + wi*32 + wop])[hi] = Wv[idx];
  }
  if(tid < 32){
    bs2[tid]    = make_float2(bq[tid], bq[tid+32]);
    bs2[32+tid] = make_float2(bk[tid], bk[tid+32]);
    bs2[64+tid] = make_float2(bv[tid], bv[tid+32]);
  }
  __syncthreads();

  int op = tid & 31;
  int ng = (tid >> 5) << 3;
  U2 acc[3][8];
  #pragma unroll
  for(int m=0;m<3;m++){
    U2 b0; b0.f = bs2[m*32+op];
    #pragma unroll
    for(int g=0;g<8;g++) acc[m][g] = b0;
  }
  const unsigned long long* wsu = (const unsigned long long*)ws2;
  #pragma unroll 4
  for(int i=0; i<64; i++){
    unsigned long long w0 = wsu[0*2048 + i*32 + op];
    unsigned long long w1 = wsu[1*2048 + i*32 + op];
    unsigned long long w2 = wsu[2*2048 + i*32 + op];
    #pragma unroll
    for(int g=0;g<8;g++){
      float xv = xsf[(ng+g)*64 + i];
      unsigned long long xx; PACK2(xx, xv);
      FMA2(acc[0][g].u, xx, w0);
      FMA2(acc[1][g].u, xx, w1);
      FMA2(acc[2][g].u, xx, w2);
    }
  }
  #pragma unroll
  for(int g=0;g<8;g++){
    int n = nb + ng + g;
    if(n < NN){
      float q0 = acc[0][g].f.x, q1 = acc[0][g].f.y;
      q0 = (q0 > 0.f) ? (q0 + 1.f) : __expf(q0);
      q1 = (q1 > 0.f) ? (q1 + 1.f) : __expf(q1);
      g_Q[n*64+op] = q0; g_Q[n*64+op+32] = q1;
      float k0 = acc[1][g].f.x, k1 = acc[1][g].f.y;
      k0 = (k0 > 0.f) ? (k0 + 1.f) : __expf(k0);
      k1 = (k1 > 0.f) ? (k1 + 1.f) : __expf(k1);
      g_Kh[n*64+op] = __float2half_rn(k0); g_Kh[n*64+op+32] = __float2half_rn(k1);
      float v0 = acc[2][g].f.x, v1 = acc[2][g].f.y;
      g_V[n*64+op] = v0; g_V[n*64+op+32] = v1;
      g_Vh[n*64+op] = __float2half_rn(v0); g_Vh[n*64+op+32] = __float2half_rn(v1);
    }
  }
}

// ---------------- output GEMM: 32-node tiles, 625 blocks ----------------
#define SMEMO (8192 + 16384 + 256)
__global__ void __launch_bounds__(256,6) k_gemmO(const float* __restrict__ Wo,
                                                 const float* __restrict__ bo,
                                                 float* __restrict__ dout){
  extern __shared__ __align__(16) char dsm[];
  float*  xsf = (float*)dsm;                        // [32][64]
  float2* ws2 = (float2*)(dsm + 8192);
  float2* bs2 = (float2*)(dsm + 8192 + 16384);
  int nb = blockIdx.x*32;
  int tid = threadIdx.x;
  for(int idx = tid; idx < 2048; idx += 256)
    xsf[idx] = g_hidden[nb*64 + idx];
  for(int idx = tid; idx < 4096; idx += 256){
    int wi = idx >> 6, wo = idx & 63;
    ((float*)&ws2[wi*32 + (wo & 31)])[wo >> 5] = Wo[idx];
  }
  if(tid < 32) bs2[tid] = make_float2(bo[tid], bo[tid+32]);
  __syncthreads();

  int op = tid & 31;
  int ng = (tid >> 5) << 2;   // 8 warps x 4 nodes = 32
  U2 acc[4];
  { U2 b0; b0.f = bs2[op];
    #pragma unroll
    for(int g=0;g<4;g++) acc[g] = b0; }
  const unsigned long long* wsu = (const unsigned long long*)ws2;
  #pragma unroll 8
  for(int i=0; i<64; i++){
    unsigned long long w0 = wsu[i*32 + op];
    #pragma unroll
    for(int g=0;g<4;g++){
      float xv = xsf[(ng+g)*64 + i];
      unsigned long long xx; PACK2(xx, xv);
      FMA2(acc[g].u, xx, w0);
    }
  }
  #pragma unroll
  for(int g=0;g<4;g++){
    int n = nb + ng + g;
    dout[n*64+op]    = acc[g].f.x;
    dout[n*64+op+32] = acc[g].f.y;
  }
}

// ---------------- hop 1: pipelined edge loop (idx 2-ahead, data 1-ahead) ----------------
__global__ void __launch_bounds__(256) k_pass1(const float* __restrict__ hopwise,
                                               const float* __restrict__ headwise){
  __shared__ float sgam[8];
  __shared__ float shop0;
  int tid = threadIdx.x;
  if(tid < 8){
    float mx = -1e30f;
    for(int hh=0; hh<8; hh++) mx = fmaxf(mx, headwise[hh*2]);
    float ss = 0.f;
    for(int hh=0; hh<8; hh++) ss += expf(headwise[hh*2]-mx);
    sgam[tid] = hopwise[1] * expf(headwise[tid*2]-mx) / ss;
  }
  if(tid == 8) shop0 = hopwise[0];
  __syncthreads();

  int n    = (blockIdx.x*256 + tid) >> 5;
  int lane = tid & 31;
  int h8   = (lane >> 2) << 3;
  int beg = colp(n), end = colp(n+1);
  U2 m0p[4], m1p[4];
  #pragma unroll
  for(int j=0;j<4;j++){ m0p[j].f = make_float2(0.f,0.f); m1p[j].f = make_float2(0.f,0.f); }
  float ka0 = 0.f, ka1 = 0.f;

  // pipeline state: current data (kh,vv,n1); next indices (r2,n2)
  __half2 kh = __floats2half2_rn(0.f,0.f);
  uint4 vv = make_uint4(0,0,0,0);
  float n1 = 0.f;
  int r2 = 0; float n2 = 0.f;
  if(beg < end){
    int r1 = g_srow[beg]; n1 = g_snorm[beg];
    kh = *(const __half2*)&g_Kh[r1*64 + 2*lane];
    vv = *(const uint4*)  &g_Vh[r1*64 + h8];
  }
  if(beg+1 < end){ r2 = g_srow[beg+1]; n2 = g_snorm[beg+1]; }

  for(int e=beg; e<end; e++){
    // prefetch indices e+2
    int r3 = 0; float n3 = 0.f;
    if(e+2 < end){ r3 = g_srow[e+2]; n3 = g_snorm[e+2]; }
    // prefetch data e+1
    __half2 kh2 = kh; uint4 vv2 = vv;
    if(e+1 < end){
      kh2 = *(const __half2*)&g_Kh[r2*64 + 2*lane];
      vv2 = *(const uint4*)  &g_Vh[r2*64 + h8];
    }
    // compute current
    float2 kf = __half22float2(kh);
    float a0 = n1*kf.x, a1 = n1*kf.y;
    ka0 += a0; ka1 += a1;
    unsigned long long A0, A1; PACK2(A0, a0); PACK2(A1, a1);
    U2 v01, v23, v45, v67;
    v01.f = __half22float2(*(__half2*)&vv.x);
    v23.f = __half22float2(*(__half2*)&vv.y);
    v45.f = __half22float2(*(__half2*)&vv.z);
    v67.f = __half22float2(*(__half2*)&vv.w);
    FMA2(m0p[0].u, A0, v01.u); FMA2(m0p[1].u, A0, v23.u);
    FMA2(m0p[2].u, A0, v45.u); FMA2(m0p[3].u, A0, v67.u);
    FMA2(m1p[0].u, A1, v01.u); FMA2(m1p[1].u, A1, v23.u);
    FMA2(m1p[2].u, A1, v45.u); FMA2(m1p[3].u, A1, v67.u);
    kh = kh2; vv = vv2; n1 = n2; r2 = r3; n2 = n3;
  }

  float m0[8], m1[8];
  #pragma unroll
  for(int j=0;j<4;j++){
    m0[2*j] = m0p[j].f.x; m0[2*j+1] = m0p[j].f.y;
    m1[2*j] = m1p[j].f.x; m1[2*j+1] = m1p[j].f.y;
  }
  {
    union { uint4 u; __half2 h[4]; } p;
    p.h[0]=__floats2half2_rn(m0[0],m0[1]); p.h[1]=__floats2half2_rn(m0[2],m0[3]);
    p.h[2]=__floats2half2_rn(m0[4],m0[5]); p.h[3]=__floats2half2_rn(m0[6],m0[7]);
    *(uint4*)&g_M1h[(size_t)n*512 + lane*8] = p.u;
    p.h[0]=__floats2half2_rn(m1[0],m1[1]); p.h[1]=__floats2half2_rn(m1[2],m1[3]);
    p.h[2]=__floats2half2_rn(m1[4],m1[5]); p.h[3]=__floats2half2_rn(m1[6],m1[7]);
    *(uint4*)&g_M1h[(size_t)n*512 + 256 + lane*8] = p.u;
  }
  *(__half2*)&g_K1h[n*64 + 2*lane] = __floats2half2_rn(ka0, ka1);

  float2 qv = *(const float2*)&g_Q[n*64 + 2*lane];
  float p[8];
  #pragma unroll
  for(int j=0;j<8;j++) p[j] = qv.x*m0[j] + qv.y*m1[j];
  #pragma unroll
  for(int j=0;j<8;j++){
    p[j] += __shfl_xor_sync(FULLMASK, p[j], 1);
    p[j] += __shfl_xor_sync(FULLMASK, p[j], 2);
  }
  float c = qv.x*ka0 + qv.y*ka1;
  c += __shfl_xor_sync(FULLMASK, c, 1);
  c += __shfl_xor_sync(FULLMASK, c, 2);
  int h = lane >> 2, sub = lane & 3;
  if(sub < 2){
    bool lo = (sub == 0);
    float r0 = lo ? p[0] : p[4];
    float r1 = lo ? p[1] : p[5];
    float r2v = lo ? p[2] : p[6];
    float r3v = lo ? p[3] : p[7];
    float inv = sgam[h] / (c + CSTF);
    float hp0 = shop0;
    const float4 vvv = *(const float4*)&g_V[n*64 + h*8 + sub*4];
    float4 hv;
    hv.x = fmaf(vvv.x, hp0, inv*r0);
    hv.y = fmaf(vvv.y, hp0, inv*r1);
    hv.z = fmaf(vvv.z, hp0, inv*r2v);
    hv.w = fmaf(vvv.w, hp0, inv*r3v);
    *(float4*)&g_hidden[n*64 + h*8 + sub*4] = hv;
  }
  if(lane == 0) g_cur[n] = 0;
}

// ---------------- hop 2: pipelined edge loop, f32x2 accumulation ----------------
__global__ void __launch_bounds__(256) k_pass3(const float* __restrict__ hopwise,
                                               const float* __restrict__ headwise){
  __shared__ float sgam[8];
  int tid = threadIdx.x;
  if(tid < 8){
    float mx = -1e30f;
    for(int hh=0; hh<8; hh++) mx = fmaxf(mx, headwise[hh*2+1]);
    float ss = 0.f;
    for(int hh=0; hh<8; hh++) ss += expf(headwise[hh*2+1]-mx);
    sgam[tid] = hopwise[2] * expf(headwise[tid*2+1]-mx) / ss;
  }
  __syncthreads();

  int n    = (blockIdx.x*256 + tid) >> 5;
  int lane = tid & 31;
  int beg = colp(n), end = colp(n+1);
  U2 ma[4], mb[4], kap;
  #pragma unroll
  for(int j=0;j<4;j++){ ma[j].f = make_float2(0.f,0.f); mb[j].f = make_float2(0.f,0.f); }
  kap.f = make_float2(0.f,0.f);

  uint4 a = make_uint4(0,0,0,0), b = make_uint4(0,0,0,0);
  __half2 kv = __floats2half2_rn(0.f,0.f);
  float n1 = 0.f;
  int r2 = 0; float n2 = 0.f;
  if(beg < end){
    int r1 = g_srow[beg]; n1 = g_snorm[beg];
    const __half* Mr = &g_M1h[(size_t)r1*512];
    a = *(const uint4*)(Mr + lane*8);
    b = *(const uint4*)(Mr + 256 + lane*8);
    kv = *(const __half2*)&g_K1h[r1*64 + 2*lane];
  }
  if(beg+1 < end){ r2 = g_srow[beg+1]; n2 = g_snorm[beg+1]; }

  for(int e=beg; e<end; e++){
    int r3 = 0; float n3 = 0.f;
    if(e+2 < end){ r3 = g_srow[e+2]; n3 = g_snorm[e+2]; }
    uint4 na = a, nb2 = b; __half2 nkv = kv;
    if(e+1 < end){
      const __half* Mr = &g_M1h[(size_t)r2*512];
      na  = *(const uint4*)(Mr + lane*8);
      nb2 = *(const uint4*)(Mr + 256 + lane*8);
      nkv = *(const __half2*)&g_K1h[r2*64 + 2*lane];
    }
    unsigned long long N2; PACK2(N2, n1);
    U2 t;
    t.f = __half22float2(*(__half2*)&a.x); FMA2(ma[0].u, N2, t.u);
    t.f = __half22float2(*(__half2*)&a.y); FMA2(ma[1].u, N2, t.u);
    t.f = __half22float2(*(__half2*)&a.z); FMA2(ma[2].u, N2, t.u);
    t.f = __half22float2(*(__half2*)&a.w); FMA2(ma[3].u, N2, t.u);
    t.f = __half22float2(*(__half2*)&b.x); FMA2(mb[0].u, N2, t.u);
    t.f = __half22float2(*(__half2*)&b.y); FMA2(mb[1].u, N2, t.u);
    t.f = __half22float2(*(__half2*)&b.z); FMA2(mb[2].u, N2, t.u);
    t.f = __half22float2(*(__half2*)&b.w); FMA2(mb[3].u, N2, t.u);
    t.f = __half22float2(kv);              FMA2(kap.u,  N2, t.u);
    a = na; b = nb2; kv = nkv; n1 = n2; r2 = r3; n2 = n3;
  }

  float2 qv = *(const float2*)&g_Q[n*64 + 2*lane];
  float p[8];
  #pragma unroll
  for(int j=0;j<4;j++){
    p[2*j]   = qv.x*ma[j].f.x + qv.y*mb[j].f.x;
    p[2*j+1] = qv.x*ma[j].f.y + qv.y*mb[j].f.y;
  }
  #pragma unroll
  for(int j=0;j<8;j++){
    p[j] += __shfl_xor_sync(FULLMASK, p[j], 1);
    p[j] += __shfl_xor_sync(FULLMASK, p[j], 2);
  }
  float c = qv.x*kap.f.x + qv.y*kap.f.y;
  c += __shfl_xor_sync(FULLMASK, c, 1);
  c += __shfl_xor_sync(FULLMASK, c, 2);
  int h = lane >> 2, sub = lane & 3;
  if(sub < 2){
    bool lo = (sub == 0);
    float r0 = lo ? p[0] : p[4];
    float r1 = lo ? p[1] : p[5];
    float r2v = lo ? p[2] : p[6];
    float r3v = lo ? p[3] : p[7];
    float inv = sgam[h] / (c + CSTF);
    float4* hp = (float4*)&g_hidden[n*64 + h*8 + sub*4];
    float4 hv = *hp;
    hv.x += inv*r0; hv.y += inv*r1; hv.z += inv*r2v; hv.w += inv*r3v;
    *hp = hv;
  }
}

// ---------------- launch ----------------
extern "C" void kernel_launch(void* const* d_in, const int* in_sizes, int n_in,
                              void* d_out, int out_size){
  const float* x        = (const float*)d_in[0];
  const int*   ei       = (const int*)  d_in[1];
  const float* Wq       = (const float*)d_in[3];
  const float* bq       = (const float*)d_in[4];
  const float* Wk       = (const float*)d_in[5];
  const float* bk       = (const float*)d_in[6];
  const float* Wv       = (const float*)d_in[7];
  const float* bv       = (const float*)d_in[8];
  const float* Wo       = (const float*)d_in[9];
  const float* bo       = (const float*)d_in[10];
  const float* hopwise  = (const float*)d_in[11];
  const float* headwise = (const float*)d_in[12];
  float* out = (float*)d_out;

  cudaFuncSetAttribute(k_fused, cudaFuncAttributeMaxDynamicSharedMemorySize, SMEMQKV);

  k_fused <<<CSRB + GEMMB, 256, SMEMQKV>>>(ei, x, Wq, bq, Wk, bk, Wv, bv);
  k_pass1 <<<NN/8, 256>>>(hopwise, headwise);
  k_pass3 <<<NN/8, 256>>>(hopwise, headwise);
  k_gemmO <<<NN/32, 256, SMEMO>>>(Wo, bo, out);
}

// round 9
// speedup vs baseline: 1.1253x; 1.1253x over previous
#include <cuda_runtime.h>
#include <cuda_fp16.h>

#define NN 20000
#define NE 320000
#define NB 25
#define SEG 800
#define FULLMASK 0xffffffffu
#define CSTF 1e-5f
#define CSRB 148
#define GEMMB 313

#define FMA2(acc, a, b) asm("fma.rn.f32x2 %0, %1, %2, %0;" : "+l"(acc) : "l"(a), "l"(b))
#define PACK2(xx, xv)   asm("mov.b64 %0, {%1, %1};" : "=l"(xx) : "f"(xv))

union U2 { unsigned long long u; float2 f; };

// ---------------- device scratch (static; every call restores zeros) ----------------
__device__ float  g_Q[NN*64];
__device__ __half g_Kh[NN*64];
__device__ __half g_Vh[NN*64];
__device__ float  g_V[NN*64];
__device__ float  g_hidden[NN*64];
__device__ __half g_M1h[(size_t)NN*512];
__device__ __half g_K1h[NN*64];
__device__ float  g_deginv[NN];
__device__ int    g_cnt[NN];
__device__ int    g_cur[NN];
__device__ int    g_colptr[NN+1];
__device__ int    g_bsum[NB];
__device__ int    g_boff[NB+1];
__device__ int    g_srow[NE];
__device__ float  g_snorm[NE];
__device__ volatile int g_ph1, g_ph2, g_ph3;

__device__ __forceinline__ void detect64(const int* __restrict__ ei, int tid, int* s64){
  if(tid < 32){
    bool z = (ei[2*(tid*9973)+1] == 0);
    unsigned bal = __ballot_sync(FULLMASK, z);
    if(tid==0) *s64 = (bal == FULLMASK) ? 1 : 0;
  }
}

__device__ __forceinline__ int colp(int i){
  return g_colptr[i] + g_boff[i/SEG];
}

// ============ fused launch: CSR builder blocks + QKV GEMM blocks ============
#define SMEMQKV (16896 + 49152 + 768)
__global__ void __launch_bounds__(256,3) k_fused(const int* __restrict__ ei,
    const float* __restrict__ x,
    const float* __restrict__ Wq, const float* __restrict__ bq,
    const float* __restrict__ Wk, const float* __restrict__ bk,
    const float* __restrict__ Wv, const float* __restrict__ bv){
  extern __shared__ __align__(16) char dsm[];
  int tid = threadIdx.x;
  int bid = blockIdx.x;

  if(bid < CSRB){
    // -------- CSR builder --------
    int* s     = (int*)dsm;
    int* wtot  = (int*)(dsm + SEG*4);
    int* ps64  = (int*)(dsm + SEG*4 + 32);
    int* sboff = (int*)(dsm + SEG*4 + 64);
    detect64(ei, tid, ps64);
    __syncthreads();
    int s64 = *ps64;

    // phase 1: degree histogram
    for(int e = bid*256 + tid; e < NE; e += CSRB*256){
      int c = s64 ? ei[2*(NE+e)] : ei[NE+e];
      atomicAdd(&g_cnt[c], 1);
    }
    __threadfence();
    __syncthreads();
    if(tid == 0){
      atomicAdd((int*)&g_ph1, 1);
      while(g_ph1 < CSRB) {}
    }
    __syncthreads();
    __threadfence();

    // phase 2: per-segment scan + deginv; zero g_cnt
    if(bid < NB){
      for(int i=tid; i<SEG; i+=256){ s[i] = __ldcg(&g_cnt[bid*SEG+i]); g_cnt[bid*SEG+i] = 0; }
      __syncthreads();
      int c0=0,c1=0,c2=0,c3=0,v=0;
      if(tid < 200){
        c0=s[4*tid]; c1=s[4*tid+1]; c2=s[4*tid+2]; c3=s[4*tid+3];
        v = c0+c1+c2+c3;
      }
      int lane = tid & 31, wid = tid >> 5;
      int xx = v;
      #pragma unroll
      for(int off=1; off<32; off<<=1){ int y=__shfl_up_sync(FULLMASK,xx,off); if(lane>=off) xx+=y; }
      if(lane==31) wtot[wid] = xx;
      __syncthreads();
      if(tid < 32){
        int w = (tid < 7) ? wtot[tid] : 0;
        #pragma unroll
        for(int off=1; off<32; off<<=1){ int y=__shfl_up_sync(FULLMASK,w,off); if(tid>=off) w+=y; }
        if(tid < 7) wtot[tid] = w;
        if(tid == 6) g_bsum[bid] = w;
      }
      __syncthreads();
      if(tid < 200){
        int pre = xx - v + (wid>0 ? wtot[wid-1] : 0);
        int base = bid*SEG + 4*tid;
        g_colptr[base+0] = pre;
        g_colptr[base+1] = pre + c0;
        g_colptr[base+2] = pre + c0 + c1;
        g_colptr[base+3] = pre + c0 + c1 + c2;
        g_deginv[base+0] = c0 ? rsqrtf((float)c0) : 0.f;
        g_deginv[base+1] = c1 ? rsqrtf((float)c1) : 0.f;
        g_deginv[base+2] = c2 ? rsqrtf((float)c2) : 0.f;
        g_deginv[base+3] = c3 ? rsqrtf((float)c3) : 0.f;
      }
    }
    __threadfence();
    __syncthreads();
    if(tid == 0){
      atomicAdd((int*)&g_ph2, 1);
      while(g_ph2 < CSRB) {}
      if(bid == 0) g_ph1 = 0;
    }
    __syncthreads();
    __threadfence();

    // phase 3: block offsets + scatter
    if(tid < 32){
      int v = (tid < NB) ? __ldcg(&g_bsum[tid]) : 0;
      int xx = v;
      #pragma unroll
      for(int off=1; off<32; off<<=1){ int y=__shfl_up_sync(FULLMASK,xx,off); if(tid>=off) xx+=y; }
      if(tid < NB) sboff[tid] = xx - v;
      if(bid == 0){
        if(tid < NB) g_boff[tid] = xx - v;
        if(tid == 31) g_boff[NB] = NE;
      }
    }
    __syncthreads();
    for(int e = bid*256 + tid; e < NE; e += CSRB*256){
      int r = s64 ? ei[2*e]      : ei[e];
      int c = s64 ? ei[2*(NE+e)] : ei[NE+e];
      int pos = __ldcg(&g_colptr[c]) + sboff[c/SEG] + atomicAdd(&g_cur[c], 1);
      g_srow[pos]  = r;
      g_snorm[pos] = __ldcg(&g_deginv[r]) * __ldcg(&g_deginv[c]);
    }
    __threadfence();
    __syncthreads();
    if(tid == 0){
      atomicAdd((int*)&g_ph3, 1);
      if(bid == 0){
        while(g_ph3 < CSRB) {}
        g_ph2 = 0; g_ph3 = 0;
      }
    }
    return;
  }

  // -------- QKV GEMM: node-paired FMA2, transposed x tile --------
  float*  xst = (float*)dsm;                        // [i*66 + n], 64x66
  float2* ws2 = (float2*)(dsm + 16896);             // [m*2048 + i*32 + op] = (W[i][op], W[i][op+32])
  float2* bs2 = (float2*)(dsm + 16896 + 49152);
  int nb = (bid - CSRB)*64;
  for(int idx = tid; idx < 4096; idx += 256){
    int n = idx >> 6, i = idx & 63;
    xst[i*66 + n] = (nb+n < NN) ? x[(nb+n)*64 + i] : 0.f;
    int wi = idx >> 6, wo = idx & 63;
    int wop = wo & 31, hi = wo >> 5;
    ((float*)&ws2[0*2048 + wi*32 + wop])[hi] = Wq[idx];
    ((float*)&ws2[1*2048 + wi*32 + wop])[hi] = Wk[idx];
    ((float*)&ws2[2*2048 + wi*32 + wop])[hi] = Wv[idx];
  }
  if(tid < 32){
    bs2[tid]    = make_float2(bq[tid], bq[tid+32]);
    bs2[32+tid] = make_float2(bk[tid], bk[tid+32]);
    bs2[64+tid] = make_float2(bv[tid], bv[tid+32]);
  }
  __syncthreads();

  int op = tid & 31;
  int ng = (tid >> 5) << 3;
  U2 a0[3][4], a1[3][4];     // [mat][node-pair]: a0 -> output op, a1 -> op+32
  #pragma unroll
  for(int m=0;m<3;m++){
    float2 bb = bs2[m*32+op];
    unsigned long long p0, p1; PACK2(p0, bb.x); PACK2(p1, bb.y);
    #pragma unroll
    for(int g=0;g<4;g++){ a0[m][g].u = p0; a1[m][g].u = p1; }
  }

  const unsigned long long* wsu = (const unsigned long long*)ws2;
  #pragma unroll 2
  for(int i=0; i<64; i++){
    U2 wq, wk, wv;
    wq.u = wsu[0*2048 + i*32 + op];
    wk.u = wsu[1*2048 + i*32 + op];
    wv.u = wsu[2*2048 + i*32 + op];
    unsigned long long q0,q1,k0,k1,v0,v1;
    PACK2(q0, wq.f.x); PACK2(q1, wq.f.y);
    PACK2(k0, wk.f.x); PACK2(k1, wk.f.y);
    PACK2(v0, wv.f.x); PACK2(v1, wv.f.y);
    const unsigned long long* xp = (const unsigned long long*)&xst[i*66 + ng];
    #pragma unroll
    for(int g=0;g<4;g++){
      unsigned long long xx = xp[g];   // (x[n0], x[n1]) broadcast LDS.64
      FMA2(a0[0][g].u, xx, q0); FMA2(a1[0][g].u, xx, q1);
      FMA2(a0[1][g].u, xx, k0); FMA2(a1[1][g].u, xx, k1);
      FMA2(a0[2][g].u, xx, v0); FMA2(a1[2][g].u, xx, v1);
    }
  }

  #pragma unroll
  for(int g=0;g<4;g++){
    int n0 = nb + ng + 2*g, n1 = n0 + 1;
    // node n0: a0[m][g].f.x (op), a1[m][g].f.x (op+32); node n1: .y
    #pragma unroll
    for(int t=0;t<2;t++){
      int n = t ? n1 : n0;
      if(n < NN){
        float qa = t ? a0[0][g].f.y : a0[0][g].f.x;
        float qb = t ? a1[0][g].f.y : a1[0][g].f.x;
        qa = (qa > 0.f) ? (qa + 1.f) : __expf(qa);
        qb = (qb > 0.f) ? (qb + 1.f) : __expf(qb);
        g_Q[n*64+op] = qa; g_Q[n*64+op+32] = qb;
        float ka = t ? a0[1][g].f.y : a0[1][g].f.x;
        float kb = t ? a1[1][g].f.y : a1[1][g].f.x;
        ka = (ka > 0.f) ? (ka + 1.f) : __expf(ka);
        kb = (kb > 0.f) ? (kb + 1.f) : __expf(kb);
        g_Kh[n*64+op] = __float2half_rn(ka); g_Kh[n*64+op+32] = __float2half_rn(kb);
        float va = t ? a0[2][g].f.y : a0[2][g].f.x;
        float vb = t ? a1[2][g].f.y : a1[2][g].f.x;
        g_V[n*64+op] = va; g_V[n*64+op+32] = vb;
        g_Vh[n*64+op] = __float2half_rn(va); g_Vh[n*64+op+32] = __float2half_rn(vb);
      }
    }
  }
}

// ---------------- output GEMM: node-paired FMA2, 64-node tiles ----------------
#define SMEMO (16896 + 16384 + 256)
__global__ void __launch_bounds__(256,3) k_gemmO(const float* __restrict__ Wo,
                                                 const float* __restrict__ bo,
                                                 float* __restrict__ dout){
  extern __shared__ __align__(16) char dsm[];
  float*  xst = (float*)dsm;                        // [i*66 + n]
  float2* ws2 = (float2*)(dsm + 16896);
  float2* bs2 = (float2*)(dsm + 16896 + 16384);
  int nb = blockIdx.x*64;
  int tid = threadIdx.x;
  for(int idx = tid; idx < 4096; idx += 256){
    int n = idx >> 6, i = idx & 63;
    xst[i*66 + n] = (nb+n < NN) ? g_hidden[(nb+n)*64 + i] : 0.f;
    int wi = idx >> 6, wo = idx & 63;
    ((float*)&ws2[wi*32 + (wo & 31)])[wo >> 5] = Wo[idx];
  }
  if(tid < 32) bs2[tid] = make_float2(bo[tid], bo[tid+32]);
  __syncthreads();

  int op = tid & 31;
  int ng = (tid >> 5) << 3;
  U2 a0[4], a1[4];
  { float2 bb = bs2[op];
    unsigned long long p0, p1; PACK2(p0, bb.x); PACK2(p1, bb.y);
    #pragma unroll
    for(int g=0;g<4;g++){ a0[g].u = p0; a1[g].u = p1; } }
  const unsigned long long* wsu = (const unsigned long long*)ws2;
  #pragma unroll 4
  for(int i=0; i<64; i++){
    U2 w; w.u = wsu[i*32 + op];
    unsigned long long w0, w1; PACK2(w0, w.f.x); PACK2(w1, w.f.y);
    const unsigned long long* xp = (const unsigned long long*)&xst[i*66 + ng];
    #pragma unroll
    for(int g=0;g<4;g++){
      unsigned long long xx = xp[g];
      FMA2(a0[g].u, xx, w0);
      FMA2(a1[g].u, xx, w1);
    }
  }
  #pragma unroll
  for(int g=0;g<4;g++){
    int n0 = nb + ng + 2*g, n1 = n0 + 1;
    if(n0 < NN){ dout[n0*64+op] = a0[g].f.x; dout[n0*64+op+32] = a1[g].f.x; }
    if(n1 < NN){ dout[n1*64+op] = a0[g].f.y; dout[n1*64+op+32] = a1[g].f.y; }
  }
}

// ---------------- pass1 edge body ----------------
__device__ __forceinline__ void p1edge(float nrm, __half2 kh, uint4 vv,
                                       float& ka0, float& ka1, U2* m0p, U2* m1p){
  float2 kf = __half22float2(kh);
  float a0 = nrm*kf.x, a1 = nrm*kf.y;
  ka0 += a0; ka1 += a1;
  unsigned long long A0, A1; PACK2(A0, a0); PACK2(A1, a1);
  U2 v01, v23, v45, v67;
  v01.f = __half22float2(*(__half2*)&vv.x);
  v23.f = __half22float2(*(__half2*)&vv.y);
  v45.f = __half22float2(*(__half2*)&vv.z);
  v67.f = __half22float2(*(__half2*)&vv.w);
  FMA2(m0p[0].u, A0, v01.u); FMA2(m0p[1].u, A0, v23.u);
  FMA2(m0p[2].u, A0, v45.u); FMA2(m0p[3].u, A0, v67.u);
  FMA2(m1p[0].u, A1, v01.u); FMA2(m1p[1].u, A1, v23.u);
  FMA2(m1p[2].u, A1, v45.u); FMA2(m1p[3].u, A1, v67.u);
}

// ---------------- hop 1: unroll-2 edge loop ----------------
__global__ void __launch_bounds__(256) k_pass1(const float* __restrict__ hopwise,
                                               const float* __restrict__ headwise){
  __shared__ float sgam[8];
  __shared__ float shop0;
  int tid = threadIdx.x;
  if(tid < 8){
    float mx = -1e30f;
    for(int hh=0; hh<8; hh++) mx = fmaxf(mx, headwise[hh*2]);
    float ss = 0.f;
    for(int hh=0; hh<8; hh++) ss += expf(headwise[hh*2]-mx);
    sgam[tid] = hopwise[1] * expf(headwise[tid*2]-mx) / ss;
  }
  if(tid == 8) shop0 = hopwise[0];
  __syncthreads();

  int n    = (blockIdx.x*256 + tid) >> 5;
  int lane = tid & 31;
  int h8   = (lane >> 2) << 3;
  int beg = colp(n), end = colp(n+1);
  U2 m0p[4], m1p[4];
  #pragma unroll
  for(int j=0;j<4;j++){ m0p[j].f = make_float2(0.f,0.f); m1p[j].f = make_float2(0.f,0.f); }
  float ka0 = 0.f, ka1 = 0.f;

  int e = beg;
  for(; e+1 < end; e += 2){
    int rA = g_srow[e];   float nA = g_snorm[e];
    int rB = g_srow[e+1]; float nB = g_snorm[e+1];
    __half2 khA = *(const __half2*)&g_Kh[rA*64 + 2*lane];
    uint4   vvA = *(const uint4*)  &g_Vh[rA*64 + h8];
    __half2 khB = *(const __half2*)&g_Kh[rB*64 + 2*lane];
    uint4   vvB = *(const uint4*)  &g_Vh[rB*64 + h8];
    p1edge(nA, khA, vvA, ka0, ka1, m0p, m1p);
    p1edge(nB, khB, vvB, ka0, ka1, m0p, m1p);
  }
  if(e < end){
    int rA = g_srow[e]; float nA = g_snorm[e];
    __half2 khA = *(const __half2*)&g_Kh[rA*64 + 2*lane];
    uint4   vvA = *(const uint4*)  &g_Vh[rA*64 + h8];
    p1edge(nA, khA, vvA, ka0, ka1, m0p, m1p);
  }

  float m0[8], m1[8];
  #pragma unroll
  for(int j=0;j<4;j++){
    m0[2*j] = m0p[j].f.x; m0[2*j+1] = m0p[j].f.y;
    m1[2*j] = m1p[j].f.x; m1[2*j+1] = m1p[j].f.y;
  }
  {
    union { uint4 u; __half2 h[4]; } p;
    p.h[0]=__floats2half2_rn(m0[0],m0[1]); p.h[1]=__floats2half2_rn(m0[2],m0[3]);
    p.h[2]=__floats2half2_rn(m0[4],m0[5]); p.h[3]=__floats2half2_rn(m0[6],m0[7]);
    *(uint4*)&g_M1h[(size_t)n*512 + lane*8] = p.u;
    p.h[0]=__floats2half2_rn(m1[0],m1[1]); p.h[1]=__floats2half2_rn(m1[2],m1[3]);
    p.h[2]=__floats2half2_rn(m1[4],m1[5]); p.h[3]=__floats2half2_rn(m1[6],m1[7]);
    *(uint4*)&g_M1h[(size_t)n*512 + 256 + lane*8] = p.u;
  }
  *(__half2*)&g_K1h[n*64 + 2*lane] = __floats2half2_rn(ka0, ka1);

  float2 qv = *(const float2*)&g_Q[n*64 + 2*lane];
  float p[8];
  #pragma unroll
  for(int j=0;j<8;j++) p[j] = qv.x*m0[j] + qv.y*m1[j];
  #pragma unroll
  for(int j=0;j<8;j++){
    p[j] += __shfl_xor_sync(FULLMASK, p[j], 1);
    p[j] += __shfl_xor_sync(FULLMASK, p[j], 2);
  }
  float c = qv.x*ka0 + qv.y*ka1;
  c += __shfl_xor_sync(FULLMASK, c, 1);
  c += __shfl_xor_sync(FULLMASK, c, 2);
  int h = lane >> 2, sub = lane & 3;
  if(sub < 2){
    bool lo = (sub == 0);
    float r0 = lo ? p[0] : p[4];
    float r1 = lo ? p[1] : p[5];
    float r2 = lo ? p[2] : p[6];
    float r3 = lo ? p[3] : p[7];
    float inv = sgam[h] / (c + CSTF);
    float hp0 = shop0;
    const float4 vv = *(const float4*)&g_V[n*64 + h*8 + sub*4];
    float4 hv;
    hv.x = fmaf(vv.x, hp0, inv*r0);
    hv.y = fmaf(vv.y, hp0, inv*r1);
    hv.z = fmaf(vv.z, hp0, inv*r2);
    hv.w = fmaf(vv.w, hp0, inv*r3);
    *(float4*)&g_hidden[n*64 + h*8 + sub*4] = hv;
  }
  if(lane == 0) g_cur[n] = 0;
}

// ---------------- pass3 edge body ----------------
__device__ __forceinline__ void p3edge(float nrm, uint4 a, uint4 b, __half2 kv,
                                       U2* ma, U2* mb, U2& kap){
  unsigned long long N2; PACK2(N2, nrm);
  U2 t;
  t.f = __half22float2(*(__half2*)&a.x); FMA2(ma[0].u, N2, t.u);
  t.f = __half22float2(*(__half2*)&a.y); FMA2(ma[1].u, N2, t.u);
  t.f = __half22float2(*(__half2*)&a.z); FMA2(ma[2].u, N2, t.u);
  t.f = __half22float2(*(__half2*)&a.w); FMA2(ma[3].u, N2, t.u);
  t.f = __half22float2(*(__half2*)&b.x); FMA2(mb[0].u, N2, t.u);
  t.f = __half22float2(*(__half2*)&b.y); FMA2(mb[1].u, N2, t.u);
  t.f = __half22float2(*(__half2*)&b.z); FMA2(mb[2].u, N2, t.u);
  t.f = __half22float2(*(__half2*)&b.w); FMA2(mb[3].u, N2, t.u);
  t.f = __half22float2(kv);              FMA2(kap.u,  N2, t.u);
}

// ---------------- hop 2: unroll-2 edge loop ----------------
__global__ void __launch_bounds__(256) k_pass3(const float* __restrict__ hopwise,
                                               const float* __restrict__ headwise){
  __shared__ float sgam[8];
  int tid = threadIdx.x;
  if(tid < 8){
    float mx = -1e30f;
    for(int hh=0; hh<8; hh++) mx = fmaxf(mx, headwise[hh*2+1]);
    float ss = 0.f;
    for(int hh=0; hh<8; hh++) ss += expf(headwise[hh*2+1]-mx);
    sgam[tid] = hopwise[2] * expf(headwise[tid*2+1]-mx) / ss;
  }
  __syncthreads();

  int n    = (blockIdx.x*256 + tid) >> 5;
  int lane = tid & 31;
  int beg = colp(n), end = colp(n+1);
  U2 ma[4], mb[4], kap;
  #pragma unroll
  for(int j=0;j<4;j++){ ma[j].f = make_float2(0.f,0.f); mb[j].f = make_float2(0.f,0.f); }
  kap.f = make_float2(0.f,0.f);

  int e = beg;
  for(; e+1 < end; e += 2){
    int rA = g_srow[e];   float nA = g_snorm[e];
    int rB = g_srow[e+1]; float nB = g_snorm[e+1];
    const __half* MA = &g_M1h[(size_t)rA*512];
    const __half* MB = &g_M1h[(size_t)rB*512];
    uint4 aA = *(const uint4*)(MA + lane*8);
    uint4 bA = *(const uint4*)(MA + 256 + lane*8);
    __half2 kA = *(const __half2*)&g_K1h[rA*64 + 2*lane];
    uint4 aB = *(const uint4*)(MB + lane*8);
    uint4 bB = *(const uint4*)(MB + 256 + lane*8);
    __half2 kB = *(const __half2*)&g_K1h[rB*64 + 2*lane];
    p3edge(nA, aA, bA, kA, ma, mb, kap);
    p3edge(nB, aB, bB, kB, ma, mb, kap);
  }
  if(e < end){
    int rA = g_srow[e]; float nA = g_snorm[e];
    const __half* MA = &g_M1h[(size_t)rA*512];
    uint4 aA = *(const uint4*)(MA + lane*8);
    uint4 bA = *(const uint4*)(MA + 256 + lane*8);
    __half2 kA = *(const __half2*)&g_K1h[rA*64 + 2*lane];
    p3edge(nA, aA, bA, kA, ma, mb, kap);
  }

  float2 qv = *(const float2*)&g_Q[n*64 + 2*lane];
  float p[8];
  #pragma unroll
  for(int j=0;j<4;j++){
    p[2*j]   = qv.x*ma[j].f.x + qv.y*mb[j].f.x;
    p[2*j+1] = qv.x*ma[j].f.y + qv.y*mb[j].f.y;
  }
  #pragma unroll
  for(int j=0;j<8;j++){
    p[j] += __shfl_xor_sync(FULLMASK, p[j], 1);
    p[j] += __shfl_xor_sync(FULLMASK, p[j], 2);
  }
  float c = qv.x*kap.f.x + qv.y*kap.f.y;
  c += __shfl_xor_sync(FULLMASK, c, 1);
  c += __shfl_xor_sync(FULLMASK, c, 2);
  int h = lane >> 2, sub = lane & 3;
  if(sub < 2){
    bool lo = (sub == 0);
    float r0 = lo ? p[0] : p[4];
    float r1 = lo ? p[1] : p[5];
    float r2 = lo ? p[2] : p[6];
    float r3 = lo ? p[3] : p[7];
    float inv = sgam[h] / (c + CSTF);
    float4* hp = (float4*)&g_hidden[n*64 + h*8 + sub*4];
    float4 hv = *hp;
    hv.x += inv*r0; hv.y += inv*r1; hv.z += inv*r2; hv.w += inv*r3;
    *hp = hv;
  }
}

// ---------------- launch ----------------
extern "C" void kernel_launch(void* const* d_in, const int* in_sizes, int n_in,
                              void* d_out, int out_size){
  const float* x        = (const float*)d_in[0];
  const int*   ei       = (const int*)  d_in[1];
  const float* Wq       = (const float*)d_in[3];
  const float* bq       = (const float*)d_in[4];
  const float* Wk       = (const float*)d_in[5];
  const float* bk       = (const float*)d_in[6];
  const float* Wv       = (const float*)d_in[7];
  const float* bv       = (const float*)d_in[8];
  const float* Wo       = (const float*)d_in[9];
  const float* bo       = (const float*)d_in[10];
  const float* hopwise  = (const float*)d_in[11];
  const float* headwise = (const float*)d_in[12];
  float* out = (float*)d_out;

  cudaFuncSetAttribute(k_fused, cudaFuncAttributeMaxDynamicSharedMemorySize, SMEMQKV);
  cudaFuncSetAttribute(k_gemmO, cudaFuncAttributeMaxDynamicSharedMemorySize, SMEMO);

  k_fused <<<CSRB + GEMMB, 256, SMEMQKV>>>(ei, x, Wq, bq, Wk, bk, Wv, bv);
  k_pass1 <<<NN/8, 256>>>(hopwise, headwise);
  k_pass3 <<<NN/8, 256>>>(hopwise, headwise);
  k_gemmO <<<GEMMB, 256, SMEMO>>>(Wo, bo, out);
}